// round 15
// baseline (speedup 1.0000x reference)
#include <cuda_runtime.h>
#include <cstdint>

#define B_EV 4
#define NP 8192
#define MP 2048
#define KNN 64
#define NC (B_EV * MP)
#define R2F 0.04f
#define BIGF 1e10f
#define CAP 512
#define NCONS 140
#define CPB 59                 // max center-slots per consumer block (guarded)
#define NGRP 5                 // ceil(CPB/12)

#define XLEN (NC * 128)
#define POS_OFF XLEN
#define BATCH_OFF (XLEN + NC * 3)

typedef unsigned long long ull;

__device__ float g_centers[NC * 3];
__device__ int   g_nbr[NC * KNN];
__device__ int   g_cnt[NC];
__device__ float g_U[B_EV * NP * 64];
__device__ unsigned g_prog[B_EV];   // monotonic: +2048 per event per run
__device__ unsigned g_upre;         // monotonic: +NCONS per run

__device__ __forceinline__ float dist2(float dx, float dy, float dz) {
    return __fadd_rn(__fadd_rn(__fmul_rn(dx, dx), __fmul_rn(dy, dy)),
                     __fmul_rn(dz, dz));
}

#define FMA2(acc, a, b) \
    asm("fma.rn.f32x2 %0, %1, %2, %0;" : "+l"(acc) : "l"(a), "l"(b))
#define ADD2(dst, a, b) \
    asm("add.rn.f32x2 %0, %1, %2;" : "=l"(dst) : "l"(a), "l"(b))
#define MUL2(dst, a, b) \
    asm("mul.rn.f32x2 %0, %1, %2;" : "=l"(dst) : "l"(a), "l"(b))

__device__ __forceinline__ ull pack2(float v) {
    ull r; asm("mov.b64 %0, {%1, %1};" : "=l"(r) : "r"(__float_as_uint(v)));
    return r;
}
__device__ __forceinline__ ull packf2(float lo, float hi) {
    ull r; asm("mov.b64 %0, {%1, %2};" : "=l"(r)
        : "r"(__float_as_uint(lo)), "r"(__float_as_uint(hi)));
    return r;
}
__device__ __forceinline__ float2 unpack2(ull p) {
    unsigned lo, hi; asm("mov.b64 {%0, %1}, %2;" : "=r"(lo), "=r"(hi) : "l"(p));
    return make_float2(__uint_as_float(lo), __uint_as_float(hi));
}

__device__ __forceinline__ float max22_tree(const float* d) {
    float m[11];
#pragma unroll
    for (int k = 0; k < 11; k++) m[k] = fmaxf(d[2 * k], d[2 * k + 1]);
    const float n0 = fmaxf(m[0], m[1]), n1 = fmaxf(m[2], m[3]);
    const float n2 = fmaxf(m[4], m[5]), n3 = fmaxf(m[6], m[7]);
    const float n4 = fmaxf(m[8], m[9]);
    return fmaxf(fmaxf(fmaxf(n0, n1), fmaxf(n2, n3)), fmaxf(n4, m[10]));
}

// ============================================================================
// Fused persistent kernel. Blocks 0..3: FPS producer (one event each).
// Blocks 4..143: consumers (upre, then per-center bq + mlp, pipelined against
// FPS via monotonic progress counters). All numeric chains identical to the
// proven R7/R5 kernels -> bit-exact outputs.
// ============================================================================
__global__ __launch_bounds__(384) void fused_kernel(
    const float* __restrict__ x, const float* __restrict__ pos,
    const float* __restrict__ W1, const float* __restrict__ b1,
    const float* __restrict__ W2, const float* __restrict__ b2,
    const float* __restrict__ W3, const float* __restrict__ b3,
    float* __restrict__ out)
{
    extern __shared__ float dyn[];
    const int tid = threadIdx.x;
    const int lane = tid & 31;
    const int wid = tid >> 5;

    if (blockIdx.x < B_EV) {
        // ==================== FPS role: 384 threads x 22 pts ====================
        const int e = blockIdx.x;
        const float* pe = pos + (size_t)e * NP * 3;
        float* sx = dyn;
        float* sy = sx + NP;
        float* sz = sy + NP;
        int*   sidx = (int*)(sz + NP);
        __shared__ int s_cnt[64];
        __shared__ ull s_key[2][16];

        if (tid < 64) s_cnt[tid] = 0;
        if (tid < 8) s_key[tid >> 2][12 + (tid & 3)] = 0ull;
        __syncthreads();

        float ox[22], oy[22], oz[22];
        int cel[22];
#pragma unroll
        for (int j = 0; j < 22; j++) {
            const bool act = (j < 21) || (tid < 128);
            if (act) {
                const int g = tid + j * 384;
                ox[j] = pe[3 * g]; oy[j] = pe[3 * g + 1]; oz[j] = pe[3 * g + 2];
                int ix = (int)(ox[j] * 4.f); ix = ix < 3 ? ix : 3;
                int iy = (int)(oy[j] * 4.f); iy = iy < 3 ? iy : 3;
                int iz = (int)(oz[j] * 4.f); iz = iz < 3 ? iz : 3;
                cel[j] = ((ix >> 1) << 5) | ((iy >> 1) << 4) | ((iz >> 1) << 3) |
                         ((ix & 1) << 2) | ((iy & 1) << 1) | (iz & 1);
                atomicAdd(&s_cnt[cel[j]], 1);
            }
        }
        __syncthreads();
        if (tid == 0) {
            int run = 0;
            for (int c2 = 0; c2 < 64; c2++) { const int v = s_cnt[c2]; s_cnt[c2] = run; run += v; }
        }
        __syncthreads();
#pragma unroll
        for (int j = 0; j < 22; j++) {
            const bool act = (j < 21) || (tid < 128);
            if (act) {
                const int p = atomicAdd(&s_cnt[cel[j]], 1);
                sx[p] = ox[j]; sy[p] = oy[j]; sz[p] = oz[j];
                sidx[p] = tid + j * 384;
            }
        }
        __syncthreads();

        ull pxp[11], pyp[11], pzp[11];
        int io[22];
        float d[22];
        float tbnx = 2.f, tbny = 2.f, tbnz = 2.f, tbxx = -1.f, tbxy = -1.f, tbxz = -1.f;
        const int base = tid * 22;
#pragma unroll
        for (int j = 0; j < 11; j++) {
            int s0 = base + 2 * j;     s0 = s0 < 8191 ? s0 : 8191;
            int s1 = base + 2 * j + 1; s1 = s1 < 8191 ? s1 : 8191;
            const float ax = sx[s0], bx = sx[s1];
            const float ay = sy[s0], by = sy[s1];
            const float az = sz[s0], bz = sz[s1];
            pxp[j] = packf2(ax, bx); pyp[j] = packf2(ay, by); pzp[j] = packf2(az, bz);
            io[2 * j] = sidx[s0]; io[2 * j + 1] = sidx[s1];
            tbnx = fminf(tbnx, fminf(ax, bx)); tbxx = fmaxf(tbxx, fmaxf(ax, bx));
            tbny = fminf(tbny, fminf(ay, by)); tbxy = fmaxf(tbxy, fmaxf(ay, by));
            tbnz = fminf(tbnz, fminf(az, bz)); tbxz = fmaxf(tbxz, fmaxf(az, bz));
        }
        __syncthreads();   // sorted reads done -> repurpose buffers

        // orig-indexed position copy for O(LDS) next-center lookup
#pragma unroll
        for (int j = 0; j < 22; j++) {
            const bool act = (j < 21) || (tid < 128);
            if (act) {
                const int g = tid + j * 384;
                sx[g] = ox[j]; sy[g] = oy[j]; sz[g] = oz[j];
            }
        }

        const float c0x = pe[0], c0y = pe[1], c0z = pe[2];
        {
            const ull ncx = pack2(-c0x), ncy = pack2(-c0y), ncz = pack2(-c0z);
#pragma unroll
            for (int j = 0; j < 11; j++) {
                ull dx, dy, dz, qx, qy, qz, s1v, s2v;
                ADD2(dx, pxp[j], ncx); ADD2(dy, pyp[j], ncy); ADD2(dz, pzp[j], ncz);
                MUL2(qx, dx, dx); MUL2(qy, dy, dy); MUL2(qz, dz, dz);
                ADD2(s1v, qx, qy); ADD2(s2v, s1v, qz);
                const float2 f = unpack2(s2v);
                d[2 * j] = f.x; d[2 * j + 1] = f.y;
            }
        }
        ull mykey;
        float tdmax;
        {
            const float mm = max22_tree(d);
            tdmax = mm;
            const unsigned wb = __reduce_max_sync(0xffffffffu, __float_as_uint(mm));
            unsigned cl = 0;
#pragma unroll
            for (int t = 0; t < 22; t++)
                if (__float_as_uint(d[t]) == wb) cl = max(cl, ~(unsigned)io[t]);
            const unsigned wl = __reduce_max_sync(0xffffffffu, cl);
            mykey = ((ull)wb << 32) | wl;
        }
        if (lane == 0) s_key[0][wid] = mykey;
        if (tid == 0) {
            g_centers[(e * MP) * 3 + 0] = c0x;
            g_centers[(e * MP) * 3 + 1] = c0y;
            g_centers[(e * MP) * 3 + 2] = c0z;
        }

        for (int i = 1; i < MP; i++) {
            __syncthreads();
            const ull kk = s_key[(i - 1) & 1][lane & 15];
            const unsigned hi = (unsigned)(kk >> 32);
            const unsigned lo = (unsigned)kk;
            const unsigned mhi = __reduce_max_sync(0xffffffffu, hi);
            const unsigned mlo = __reduce_max_sync(0xffffffffu, (hi == mhi) ? lo : 0u);
            const int nxt = (int)(~mlo);

            const float nx = sx[nxt], ny = sy[nxt], nz = sz[nxt];
            if (tid == 0) {
                g_centers[(e * MP + i) * 3 + 0] = nx;
                g_centers[(e * MP + i) * 3 + 1] = ny;
                g_centers[(e * MP + i) * 3 + 2] = nz;
                if ((i & 7) == 7) {            // batched publish (8 centers)
                    __threadfence();
                    atomicAdd(&g_prog[e], 8u);
                }
            }

            const float lbx = fmaxf(fmaxf(tbnx - nx, nx - tbxx), 0.f);
            const float lby = fmaxf(fmaxf(tbny - ny, ny - tbxy), 0.f);
            const float lbz = fmaxf(fmaxf(tbnz - nz, nz - tbxz), 0.f);
            const float lb2 = ((lbx * lbx + lby * lby) + lbz * lbz) * 0.999999f;
            const bool needs = (lb2 < tdmax);

            if (__any_sync(0xffffffffu, needs)) {
                const ull ncx = pack2(-nx), ncy = pack2(-ny), ncz = pack2(-nz);
#pragma unroll
                for (int j = 0; j < 11; j++) {
                    ull dx, dy, dz, qx, qy, qz, s1v, s2v;
                    ADD2(dx, pxp[j], ncx); ADD2(dy, pyp[j], ncy); ADD2(dz, pzp[j], ncz);
                    MUL2(qx, dx, dx); MUL2(qy, dy, dy); MUL2(qz, dz, dz);
                    ADD2(s1v, qx, qy); ADD2(s2v, s1v, qz);
                    const float2 f = unpack2(s2v);
                    d[2 * j]     = fminf(d[2 * j], f.x);
                    d[2 * j + 1] = fminf(d[2 * j + 1], f.y);
                }
                const float mm = max22_tree(d);
                tdmax = mm;
                const unsigned wb = __reduce_max_sync(0xffffffffu, __float_as_uint(mm));
                unsigned cl = 0;
#pragma unroll
                for (int t = 0; t < 22; t++)
                    if (__float_as_uint(d[t]) == wb) cl = max(cl, ~(unsigned)io[t]);
                const unsigned wl = __reduce_max_sync(0xffffffffu, cl);
                mykey = ((ull)wb << 32) | wl;
            }
            if (lane == 0) s_key[i & 1][wid] = mykey;
        }
        return;
    }

    // ======================= Consumer role =======================
    const int cb = blockIdx.x - B_EV;           // 0..139
    float* sW1p = dyn;                          // 192
    float* sW2  = dyn + 192;                    // 4096
    float* sW3  = dyn + 4288;                   // 8192
    float* sb2  = dyn + 12480;                  // 64
    float* sb3  = dyn + 12544;                  // 128
    float* bqd  = dyn + 12672;                  // 12*512
    int*   bqi  = (int*)(dyn + 18816);          // 12*512
    int*   sOut = (int*)(dyn + 24960);          // 6*128
    __shared__ unsigned s_base[4];
    __shared__ unsigned s_ub;

    if (tid < 4) s_base[tid] = (*((volatile unsigned*)&g_prog[tid]) / MP) * MP;
    if (tid == 4) s_ub = (*((volatile unsigned*)&g_upre) / NCONS) * NCONS;

    // ---- upre phase (scratch: W1[0:32] in sW2, b1 in sb2) ----
    for (int i = tid; i < 2048; i += 384) sW2[i] = W1[i];
    if (tid < 64) sb2[tid] = b1[tid];
    __syncthreads();
    {
        const int r = cb * 235 + tid;
        if (tid < 235 && r < B_EV * NP) {
            float inv[32];
            const float4* xr = (const float4*)(x + (size_t)r * 32);
#pragma unroll
            for (int q = 0; q < 8; q++) {
                const float4 v = xr[q];
                inv[4 * q] = v.x; inv[4 * q + 1] = v.y;
                inv[4 * q + 2] = v.z; inv[4 * q + 3] = v.w;
            }
            float4* ur = (float4*)(g_U + (size_t)r * 64);
#pragma unroll
            for (int h = 0; h < 2; h++) {
                ull acc[16];
#pragma unroll
                for (int k = 0; k < 8; k++) {
                    const ulonglong2 bb = *(const ulonglong2*)(sb2 + h * 32 + 4 * k);
                    acc[2 * k] = bb.x; acc[2 * k + 1] = bb.y;
                }
#pragma unroll
                for (int i2 = 0; i2 < 32; i2++) {
                    const ull a = pack2(inv[i2]);
#pragma unroll
                    for (int k = 0; k < 8; k++) {
                        const ulonglong2 wv = *(const ulonglong2*)(sW2 + i2 * 64 + h * 32 + 4 * k);
                        FMA2(acc[2 * k], a, wv.x);
                        FMA2(acc[2 * k + 1], a, wv.y);
                    }
                }
#pragma unroll
                for (int k = 0; k < 8; k++) {
                    const float2 v0 = unpack2(acc[2 * k]);
                    const float2 v1 = unpack2(acc[2 * k + 1]);
                    ur[h * 8 + k] = make_float4(v0.x, v0.y, v1.x, v1.y);
                }
            }
        }
    }
    __threadfence();
    __syncthreads();
    if (tid == 0) atomicAdd(&g_upre, 1u);

    // ---- load real weights (overwrites scratch) ----
    __syncthreads();
    for (int i = tid; i < 192; i += 384) sW1p[i] = W1[2048 + i];
    for (int i = tid; i < 4096; i += 384) sW2[i] = W2[i];
    for (int i = tid; i < 8192; i += 384) sW3[i] = W3[i];
    if (tid < 64) sb2[tid] = b2[tid];
    if (tid < 128) sb3[tid] = b3[tid];
    if (tid == 0) {
        while (*((volatile unsigned*)&g_upre) < s_ub + NCONS) __nanosleep(128);
    }
    __syncthreads();
    __threadfence();

    // ---- group loop: 12 centers = 12 bq warps, then 2 mlp passes of 6 ----
    for (int g = 0; g < NGRP; g++) {
        {   // bq by warp
            const int kidx = 12 * g + wid;
            const int c = cb + NCONS * kidx;
            if (kidx < CPB && c < NC) {
                const int ev = c >> 11;
                const unsigned thr = s_base[ev] + (unsigned)(c & 2047) + 1u;
                while (*((volatile unsigned*)&g_prog[ev]) < thr) __nanosleep(128);
                __threadfence();
                const float* pe = pos + (size_t)ev * NP * 3;
                const float cx = g_centers[c * 3 + 0];
                const float cy = g_centers[c * 3 + 1];
                const float cz = g_centers[c * 3 + 2];
                float* d2 = bqd + wid * CAP;
                int*   iv = bqi + wid * CAP;
                int cnt = 0;
                const unsigned lmask = (1u << lane) - 1u;
                for (int j = lane; j < NP; j += 32) {
                    const float dv = dist2(pe[3 * j] - cx, pe[3 * j + 1] - cy,
                                           pe[3 * j + 2] - cz);
                    const bool inr = (dv <= R2F);
                    const unsigned mb = __ballot_sync(0xffffffffu, inr);
                    if (inr) {
                        const int slot = cnt + __popc(mb & lmask);
                        if (slot < CAP) { d2[slot] = dv; iv[slot] = j; }
                    }
                    cnt += __popc(mb);
                }
                const int C = (cnt < CAP) ? cnt : CAP;
                if (C <= KNN) {
                    for (int k = lane; k < KNN; k += 32)
                        g_nbr[c * KNN + k] = (k < C) ? iv[k] : 0;
                    if (lane == 0) g_cnt[c] = C;
                } else {
                    for (int s = 0; s < KNN; s++) {
                        ull best = ~0ull;
                        for (int t = lane; t < C; t += 32) {
                            const ull key = ((ull)__float_as_uint(d2[t]) << 32) | (unsigned)t;
                            best = (key < best) ? key : best;
                        }
#pragma unroll
                        for (int o = 16; o > 0; o >>= 1) {
                            const ull other = __shfl_down_sync(0xffffffffu, best, o);
                            best = (other < best) ? other : best;
                        }
                        best = __shfl_sync(0xffffffffu, best, 0);
                        const int slot = (int)(unsigned)best;
                        if (lane == 0) {
                            g_nbr[c * KNN + s] = iv[slot];
                            d2[slot] = BIGF;
                        }
                        __syncwarp();
                    }
                    if (lane == 0) g_cnt[c] = KNN;
                }
            }
        }
        __syncthreads();

        for (int p = 0; p < 2; p++) {
            sOut[tid] = 0;
            if (tid < 384) sOut[tid + 384] = 0;
            __syncthreads();

            const int kk = 12 * g + 6 * p + (tid >> 6);
            const int cc = cb + NCONS * kk;
            if (kk < CPB && cc < NC) {
                const int ev = cc >> 11;
                const int n = tid & 63;
                const bool active = (n < g_cnt[cc]);
                int* sOutC = sOut + (tid >> 6) * 128;

                const int idx = g_nbr[cc * KNN + n];
                const int row = ev * NP + idx;

                float rel[3];
                rel[0] = pos[row * 3 + 0] - g_centers[cc * 3 + 0];
                rel[1] = pos[row * 3 + 1] - g_centers[cc * 3 + 1];
                rel[2] = pos[row * 3 + 2] - g_centers[cc * 3 + 2];

                float h1[64];
                const float4* ur = (const float4*)(g_U + (size_t)row * 64);
#pragma unroll
                for (int h = 0; h < 2; h++) {
                    ull acc[16];
#pragma unroll
                    for (int q = 0; q < 8; q++) {
                        const float4 u = ur[h * 8 + q];
                        acc[2 * q]     = packf2(u.x, u.y);
                        acc[2 * q + 1] = packf2(u.z, u.w);
                    }
#pragma unroll
                    for (int i = 0; i < 3; i++) {
                        const ull a = pack2(rel[i]);
#pragma unroll
                        for (int k = 0; k < 8; k++) {
                            const ulonglong2 wv = *(const ulonglong2*)(sW1p + i * 64 + h * 32 + 4 * k);
                            FMA2(acc[2 * k], a, wv.x);
                            FMA2(acc[2 * k + 1], a, wv.y);
                        }
                    }
#pragma unroll
                    for (int k = 0; k < 16; k++) {
                        const float2 v = unpack2(acc[k]);
                        h1[h * 32 + 2 * k]     = fmaxf(v.x, 0.f);
                        h1[h * 32 + 2 * k + 1] = fmaxf(v.y, 0.f);
                    }
                }

                float h2[64];
#pragma unroll
                for (int q = 0; q < 4; q++) {
                    ull acc[8];
#pragma unroll
                    for (int k = 0; k < 4; k++) {
                        const ulonglong2 bb = *(const ulonglong2*)(sb2 + q * 16 + 4 * k);
                        acc[2 * k] = bb.x; acc[2 * k + 1] = bb.y;
                    }
#pragma unroll
                    for (int i = 0; i < 64; i++) {
                        const ull a = pack2(h1[i]);
#pragma unroll
                        for (int k = 0; k < 4; k++) {
                            const ulonglong2 wv = *(const ulonglong2*)(sW2 + i * 64 + q * 16 + 4 * k);
                            FMA2(acc[2 * k], a, wv.x);
                            FMA2(acc[2 * k + 1], a, wv.y);
                        }
                    }
#pragma unroll
                    for (int k = 0; k < 8; k++) {
                        const float2 v = unpack2(acc[k]);
                        h2[q * 16 + 2 * k]     = fmaxf(v.x, 0.f);
                        h2[q * 16 + 2 * k + 1] = fmaxf(v.y, 0.f);
                    }
                }

#pragma unroll
                for (int qd = 0; qd < 4; qd++) {
                    ull acc[16];
#pragma unroll
                    for (int k = 0; k < 8; k++) {
                        const ulonglong2 bb = *(const ulonglong2*)(sb3 + qd * 32 + 4 * k);
                        acc[2 * k] = bb.x; acc[2 * k + 1] = bb.y;
                    }
#pragma unroll
                    for (int i = 0; i < 64; i++) {
                        const ull a = pack2(h2[i]);
#pragma unroll
                        for (int k = 0; k < 8; k++) {
                            const ulonglong2 wv = *(const ulonglong2*)(sW3 + i * 128 + qd * 32 + 4 * k);
                            FMA2(acc[2 * k], a, wv.x);
                            FMA2(acc[2 * k + 1], a, wv.y);
                        }
                    }
#pragma unroll
                    for (int k = 0; k < 16; k++) {
                        const float2 v = unpack2(acc[k]);
                        float v0 = active ? fmaxf(v.x, 0.f) : 0.f;
                        float v1 = active ? fmaxf(v.y, 0.f) : 0.f;
#pragma unroll
                        for (int o = 16; o >= 4; o >>= 1) {
                            v0 = fmaxf(v0, __shfl_xor_sync(0xffffffffu, v0, o));
                            v1 = fmaxf(v1, __shfl_xor_sync(0xffffffffu, v1, o));
                        }
                        if (lane < 4) {
                            atomicMax(sOutC + qd * 32 + 2 * k,     __float_as_int(v0));
                            atomicMax(sOutC + qd * 32 + 2 * k + 1, __float_as_int(v1));
                        }
                    }
                }
            }
            __syncthreads();

            // outputs for this pass's 6 centers
            for (int i = tid; i < 768; i += 384) {
                const int k2 = 12 * g + 6 * p + i / 128;
                const int c2 = cb + NCONS * k2;
                if (k2 < CPB && c2 < NC)
                    out[(size_t)c2 * 128 + (i & 127)] = __int_as_float(sOut[i]);
            }
            if (tid < 18) {
                const int k2 = 12 * g + 6 * p + tid / 3;
                const int c2 = cb + NCONS * k2;
                if (k2 < CPB && c2 < NC)
                    out[POS_OFF + (size_t)c2 * 3 + (tid % 3)] = g_centers[c2 * 3 + (tid % 3)];
            }
            if (tid < 6) {
                const int k2 = 12 * g + 6 * p + tid;
                const int c2 = cb + NCONS * k2;
                if (k2 < CPB && c2 < NC)
                    out[BATCH_OFF + c2] = (float)(c2 >> 11);
            }
            __syncthreads();
        }
    }
}

// ============================================================================
extern "C" void kernel_launch(void* const* d_in, const int* in_sizes, int n_in,
                              void* d_out, int out_size) {
    const float* x   = (const float*)d_in[0];
    const float* pos = (const float*)d_in[1];
    const float* W1 = (const float*)d_in[3];
    const float* b1 = (const float*)d_in[4];
    const float* W2 = (const float*)d_in[5];
    const float* b2 = (const float*)d_in[6];
    const float* W3 = (const float*)d_in[7];
    const float* b3 = (const float*)d_in[8];
    float* out = (float*)d_out;

    const int smem = 4 * NP * 4;   // 131072 B (fps needs; consumers use 103 KB)
    cudaFuncSetAttribute(fused_kernel, cudaFuncAttributeMaxDynamicSharedMemorySize,
                         smem);
    fused_kernel<<<B_EV + NCONS, 384, smem>>>(x, pos, W1, b1, W2, b2, W3, b3, out);
}

// round 16
// speedup vs baseline: 1.5664x; 1.5664x over previous
#include <cuda_runtime.h>
#include <cstdint>

#define B_EV 4
#define NP 8192
#define MP 2048
#define KNN 64
#define NC (B_EV * MP)
#define R2F 0.04f
#define BIGF 1e10f
#define CAP 512
#define NCONS 140
#define JMAX 14
#define NGRP 5

#define XLEN (NC * 128)
#define POS_OFF XLEN
#define BATCH_OFF (XLEN + NC * 3)

typedef unsigned long long ull;

__device__ float g_centers[NC * 3];
__device__ int   g_nbr[NC * KNN];
__device__ int   g_cnt[NC];
__device__ float g_U[B_EV * NP * 64];
__device__ unsigned g_prog[B_EV * 32];   // padded: one 128B line per event
__device__ unsigned g_upre;              // monotonic: +NCONS per run

__device__ __forceinline__ float dist2(float dx, float dy, float dz) {
    return __fadd_rn(__fadd_rn(__fmul_rn(dx, dx), __fmul_rn(dy, dy)),
                     __fmul_rn(dz, dz));
}

#define FMA2(acc, a, b) \
    asm("fma.rn.f32x2 %0, %1, %2, %0;" : "+l"(acc) : "l"(a), "l"(b))
#define ADD2(dst, a, b) \
    asm("add.rn.f32x2 %0, %1, %2;" : "=l"(dst) : "l"(a), "l"(b))
#define MUL2(dst, a, b) \
    asm("mul.rn.f32x2 %0, %1, %2;" : "=l"(dst) : "l"(a), "l"(b))

__device__ __forceinline__ ull pack2(float v) {
    ull r; asm("mov.b64 %0, {%1, %1};" : "=l"(r) : "r"(__float_as_uint(v)));
    return r;
}
__device__ __forceinline__ ull packf2(float lo, float hi) {
    ull r; asm("mov.b64 %0, {%1, %2};" : "=l"(r)
        : "r"(__float_as_uint(lo)), "r"(__float_as_uint(hi)));
    return r;
}
__device__ __forceinline__ float2 unpack2(ull p) {
    unsigned lo, hi; asm("mov.b64 {%0, %1}, %2;" : "=r"(lo), "=r"(hi) : "l"(p));
    return make_float2(__uint_as_float(lo), __uint_as_float(hi));
}

__device__ __forceinline__ float max22_tree(const float* d) {
    float m[11];
#pragma unroll
    for (int k = 0; k < 11; k++) m[k] = fmaxf(d[2 * k], d[2 * k + 1]);
    const float n0 = fmaxf(m[0], m[1]), n1 = fmaxf(m[2], m[3]);
    const float n2 = fmaxf(m[4], m[5]), n3 = fmaxf(m[6], m[7]);
    const float n4 = fmaxf(m[8], m[9]);
    return fmaxf(fmaxf(fmaxf(n0, n1), fmaxf(n2, n3)), fmaxf(n4, m[10]));
}

// ============================================================================
// Fused persistent kernel (R15 protocol, repaired). Blocks 0..3: FPS.
// Blocks 4..143: consumers with availability-ordered schedule.
// ============================================================================
__global__ __launch_bounds__(384) void fused_kernel(
    const float* __restrict__ x, const float* __restrict__ pos,
    const float* __restrict__ W1, const float* __restrict__ b1,
    const float* __restrict__ W2, const float* __restrict__ b2,
    const float* __restrict__ W3, const float* __restrict__ b3,
    float* __restrict__ out)
{
    extern __shared__ float dyn[];
    const int tid = threadIdx.x;
    const int lane = tid & 31;
    const int wid = tid >> 5;

    if (blockIdx.x < B_EV) {
        // ==================== FPS role (bit-exact R15 code) ====================
        const int e = blockIdx.x;
        const float* pe = pos + (size_t)e * NP * 3;
        float* sx = dyn;
        float* sy = sx + NP;
        float* sz = sy + NP;
        int*   sidx = (int*)(sz + NP);
        __shared__ int s_cnt[64];
        __shared__ ull s_key[2][16];

        if (tid < 64) s_cnt[tid] = 0;
        if (tid < 8) s_key[tid >> 2][12 + (tid & 3)] = 0ull;
        __syncthreads();

        float ox[22], oy[22], oz[22];
        int cel[22];
#pragma unroll
        for (int j = 0; j < 22; j++) {
            const bool act = (j < 21) || (tid < 128);
            if (act) {
                const int g = tid + j * 384;
                ox[j] = pe[3 * g]; oy[j] = pe[3 * g + 1]; oz[j] = pe[3 * g + 2];
                int ix = (int)(ox[j] * 4.f); ix = ix < 3 ? ix : 3;
                int iy = (int)(oy[j] * 4.f); iy = iy < 3 ? iy : 3;
                int iz = (int)(oz[j] * 4.f); iz = iz < 3 ? iz : 3;
                cel[j] = ((ix >> 1) << 5) | ((iy >> 1) << 4) | ((iz >> 1) << 3) |
                         ((ix & 1) << 2) | ((iy & 1) << 1) | (iz & 1);
                atomicAdd(&s_cnt[cel[j]], 1);
            }
        }
        __syncthreads();
        if (tid == 0) {
            int run = 0;
            for (int c2 = 0; c2 < 64; c2++) { const int v = s_cnt[c2]; s_cnt[c2] = run; run += v; }
        }
        __syncthreads();
#pragma unroll
        for (int j = 0; j < 22; j++) {
            const bool act = (j < 21) || (tid < 128);
            if (act) {
                const int p = atomicAdd(&s_cnt[cel[j]], 1);
                sx[p] = ox[j]; sy[p] = oy[j]; sz[p] = oz[j];
                sidx[p] = tid + j * 384;
            }
        }
        __syncthreads();

        ull pxp[11], pyp[11], pzp[11];
        int io[22];
        float d[22];
        float tbnx = 2.f, tbny = 2.f, tbnz = 2.f, tbxx = -1.f, tbxy = -1.f, tbxz = -1.f;
        const int base = tid * 22;
#pragma unroll
        for (int j = 0; j < 11; j++) {
            int s0 = base + 2 * j;     s0 = s0 < 8191 ? s0 : 8191;
            int s1 = base + 2 * j + 1; s1 = s1 < 8191 ? s1 : 8191;
            const float ax = sx[s0], bx = sx[s1];
            const float ay = sy[s0], by = sy[s1];
            const float az = sz[s0], bz = sz[s1];
            pxp[j] = packf2(ax, bx); pyp[j] = packf2(ay, by); pzp[j] = packf2(az, bz);
            io[2 * j] = sidx[s0]; io[2 * j + 1] = sidx[s1];
            tbnx = fminf(tbnx, fminf(ax, bx)); tbxx = fmaxf(tbxx, fmaxf(ax, bx));
            tbny = fminf(tbny, fminf(ay, by)); tbxy = fmaxf(tbxy, fmaxf(ay, by));
            tbnz = fminf(tbnz, fminf(az, bz)); tbxz = fmaxf(tbxz, fmaxf(az, bz));
        }
        __syncthreads();

#pragma unroll
        for (int j = 0; j < 22; j++) {
            const bool act = (j < 21) || (tid < 128);
            if (act) {
                const int g = tid + j * 384;
                sx[g] = ox[j]; sy[g] = oy[j]; sz[g] = oz[j];
            }
        }

        const float c0x = pe[0], c0y = pe[1], c0z = pe[2];
        {
            const ull ncx = pack2(-c0x), ncy = pack2(-c0y), ncz = pack2(-c0z);
#pragma unroll
            for (int j = 0; j < 11; j++) {
                ull dx, dy, dz, qx, qy, qz, s1v, s2v;
                ADD2(dx, pxp[j], ncx); ADD2(dy, pyp[j], ncy); ADD2(dz, pzp[j], ncz);
                MUL2(qx, dx, dx); MUL2(qy, dy, dy); MUL2(qz, dz, dz);
                ADD2(s1v, qx, qy); ADD2(s2v, s1v, qz);
                const float2 f = unpack2(s2v);
                d[2 * j] = f.x; d[2 * j + 1] = f.y;
            }
        }
        ull mykey;
        float tdmax;
        {
            const float mm = max22_tree(d);
            tdmax = mm;
            const unsigned wb = __reduce_max_sync(0xffffffffu, __float_as_uint(mm));
            unsigned cl = 0;
#pragma unroll
            for (int t = 0; t < 22; t++)
                if (__float_as_uint(d[t]) == wb) cl = max(cl, ~(unsigned)io[t]);
            const unsigned wl = __reduce_max_sync(0xffffffffu, cl);
            mykey = ((ull)wb << 32) | wl;
        }
        if (lane == 0) s_key[0][wid] = mykey;
        if (tid == 0) {
            g_centers[(e * MP) * 3 + 0] = c0x;
            g_centers[(e * MP) * 3 + 1] = c0y;
            g_centers[(e * MP) * 3 + 2] = c0z;
        }

        for (int i = 1; i < MP; i++) {
            __syncthreads();
            const ull kk = s_key[(i - 1) & 1][lane & 15];
            const unsigned hi = (unsigned)(kk >> 32);
            const unsigned lo = (unsigned)kk;
            const unsigned mhi = __reduce_max_sync(0xffffffffu, hi);
            const unsigned mlo = __reduce_max_sync(0xffffffffu, (hi == mhi) ? lo : 0u);
            const int nxt = (int)(~mlo);

            const float nx = sx[nxt], ny = sy[nxt], nz = sz[nxt];
            if (tid == 0) {
                g_centers[(e * MP + i) * 3 + 0] = nx;
                g_centers[(e * MP + i) * 3 + 1] = ny;
                g_centers[(e * MP + i) * 3 + 2] = nz;
                if ((i & 15) == 15) {      // batched publish, padded counter
                    __threadfence();
                    atomicAdd(&g_prog[e * 32], 16u);
                }
            }

            const float lbx = fmaxf(fmaxf(tbnx - nx, nx - tbxx), 0.f);
            const float lby = fmaxf(fmaxf(tbny - ny, ny - tbxy), 0.f);
            const float lbz = fmaxf(fmaxf(tbnz - nz, nz - tbxz), 0.f);
            const float lb2 = ((lbx * lbx + lby * lby) + lbz * lbz) * 0.999999f;
            const bool needs = (lb2 < tdmax);

            if (__any_sync(0xffffffffu, needs)) {
                const ull ncx = pack2(-nx), ncy = pack2(-ny), ncz = pack2(-nz);
#pragma unroll
                for (int j = 0; j < 11; j++) {
                    ull dx, dy, dz, qx, qy, qz, s1v, s2v;
                    ADD2(dx, pxp[j], ncx); ADD2(dy, pyp[j], ncy); ADD2(dz, pzp[j], ncz);
                    MUL2(qx, dx, dx); MUL2(qy, dy, dy); MUL2(qz, dz, dz);
                    ADD2(s1v, qx, qy); ADD2(s2v, s1v, qz);
                    const float2 f = unpack2(s2v);
                    d[2 * j]     = fminf(d[2 * j], f.x);
                    d[2 * j + 1] = fminf(d[2 * j + 1], f.y);
                }
                const float mm = max22_tree(d);
                tdmax = mm;
                const unsigned wb = __reduce_max_sync(0xffffffffu, __float_as_uint(mm));
                unsigned cl = 0;
#pragma unroll
                for (int t = 0; t < 22; t++)
                    if (__float_as_uint(d[t]) == wb) cl = max(cl, ~(unsigned)io[t]);
                const unsigned wl = __reduce_max_sync(0xffffffffu, cl);
                mykey = ((ull)wb << 32) | wl;
            }
            if (lane == 0) s_key[i & 1][wid] = mykey;
        }
        return;
    }

    // ======================= Consumer role =======================
    const int cb = blockIdx.x - B_EV;           // 0..139
    float* sW1p = dyn;                          // 192
    float* sW2  = dyn + 192;                    // 4096
    float* sW3  = dyn + 4288;                   // 8192
    float* sb2  = dyn + 12480;                  // 64
    float* sb3  = dyn + 12544;                  // 128
    float* bqd  = dyn + 12672;                  // 12*512
    int*   bqi  = (int*)(dyn + 18816);          // 12*512
    int*   sOut = (int*)(dyn + 24960);          // 6*128
    __shared__ unsigned s_base[4];
    __shared__ unsigned s_ub;

    if (tid < 4) s_base[tid] = (*((volatile unsigned*)&g_prog[tid * 32]) / MP) * MP;
    if (tid == 4) s_ub = (*((volatile unsigned*)&g_upre) / NCONS) * NCONS;

    // ---- upre phase (scratch: W1[0:32] in sW2, b1 in sb2) ----
    for (int i = tid; i < 2048; i += 384) sW2[i] = W1[i];
    if (tid < 64) sb2[tid] = b1[tid];
    __syncthreads();
    {
        const int r = cb * 235 + tid;
        if (tid < 235 && r < B_EV * NP) {
            float inv[32];
            const float4* xr = (const float4*)(x + (size_t)r * 32);
#pragma unroll
            for (int q = 0; q < 8; q++) {
                const float4 v = xr[q];
                inv[4 * q] = v.x; inv[4 * q + 1] = v.y;
                inv[4 * q + 2] = v.z; inv[4 * q + 3] = v.w;
            }
            float4* ur = (float4*)(g_U + (size_t)r * 64);
#pragma unroll
            for (int h = 0; h < 2; h++) {
                ull acc[16];
#pragma unroll
                for (int k = 0; k < 8; k++) {
                    const ulonglong2 bb = *(const ulonglong2*)(sb2 + h * 32 + 4 * k);
                    acc[2 * k] = bb.x; acc[2 * k + 1] = bb.y;
                }
#pragma unroll
                for (int i2 = 0; i2 < 32; i2++) {
                    const ull a = pack2(inv[i2]);
#pragma unroll
                    for (int k = 0; k < 8; k++) {
                        const ulonglong2 wv = *(const ulonglong2*)(sW2 + i2 * 64 + h * 32 + 4 * k);
                        FMA2(acc[2 * k], a, wv.x);
                        FMA2(acc[2 * k + 1], a, wv.y);
                    }
                }
#pragma unroll
                for (int k = 0; k < 8; k++) {
                    const float2 v0 = unpack2(acc[2 * k]);
                    const float2 v1 = unpack2(acc[2 * k + 1]);
                    ur[h * 8 + k] = make_float4(v0.x, v0.y, v1.x, v1.y);
                }
            }
        }
    }
    __threadfence();
    __syncthreads();
    if (tid == 0) atomicAdd(&g_upre, 1u);

    // ---- load real weights (overwrites scratch) ----
    __syncthreads();
    for (int i = tid; i < 192; i += 384) sW1p[i] = W1[2048 + i];
    for (int i = tid; i < 4096; i += 384) sW2[i] = W2[i];
    for (int i = tid; i < 8192; i += 384) sW3[i] = W3[i];
    if (tid < 64) sb2[tid] = b2[tid];
    if (tid < 128) sb3[tid] = b3[tid];
    if (tid == 0) {
        while (*((volatile unsigned*)&g_upre) < s_ub + NCONS) __nanosleep(1024);
    }
    __syncthreads();
    __threadfence();

    // ---- availability-ordered groups: group m covers j = 3m..3m+2,
    //      center (e, i) with i = cb + 140*j, c = e*2048 + i ----
    for (int m = 0; m < NGRP; m++) {
        // wait threshold: largest valid j in this group
        int jv = 3 * m + 2; if (jv > JMAX) jv = JMAX;
        while (cb + 140 * jv >= 2048) jv--;           // jv >= 3m always holds
        const int ith = cb + 140 * jv;
        if (tid < 4) {
            const unsigned thr = s_base[tid] + (unsigned)ith + 1u;
            while (*((volatile unsigned*)&g_prog[tid * 32]) < thr) __nanosleep(1024);
        }
        __syncthreads();
        __threadfence();

        {   // bq: warp wid -> j = 3m + (wid>>2), e = wid&3
            const int j = 3 * m + (wid >> 2);
            const int ev = wid & 3;
            const int ii = cb + 140 * j;
            if (j <= JMAX && ii < 2048) {
                const int c = ev * 2048 + ii;
                const float* pe = pos + (size_t)ev * NP * 3;
                const float cx = g_centers[c * 3 + 0];
                const float cy = g_centers[c * 3 + 1];
                const float cz = g_centers[c * 3 + 2];
                float* d2 = bqd + wid * CAP;
                int*   iv = bqi + wid * CAP;
                int cnt = 0;
                const unsigned lmask = (1u << lane) - 1u;
                for (int jj = lane; jj < NP; jj += 32) {
                    const float dv = dist2(pe[3 * jj] - cx, pe[3 * jj + 1] - cy,
                                           pe[3 * jj + 2] - cz);
                    const bool inr = (dv <= R2F);
                    const unsigned mb = __ballot_sync(0xffffffffu, inr);
                    if (inr) {
                        const int slot = cnt + __popc(mb & lmask);
                        if (slot < CAP) { d2[slot] = dv; iv[slot] = jj; }
                    }
                    cnt += __popc(mb);
                }
                const int C = (cnt < CAP) ? cnt : CAP;
                if (C <= KNN) {
                    for (int k = lane; k < KNN; k += 32)
                        g_nbr[c * KNN + k] = (k < C) ? iv[k] : 0;
                    if (lane == 0) g_cnt[c] = C;
                } else {
                    for (int s = 0; s < KNN; s++) {
                        ull best = ~0ull;
                        for (int t = lane; t < C; t += 32) {
                            const ull key = ((ull)__float_as_uint(d2[t]) << 32) | (unsigned)t;
                            best = (key < best) ? key : best;
                        }
#pragma unroll
                        for (int o = 16; o > 0; o >>= 1) {
                            const ull other = __shfl_down_sync(0xffffffffu, best, o);
                            best = (other < best) ? other : best;
                        }
                        best = __shfl_sync(0xffffffffu, best, 0);
                        const int slot = (int)(unsigned)best;
                        if (lane == 0) {
                            g_nbr[c * KNN + s] = iv[slot];
                            d2[slot] = BIGF;
                        }
                        __syncwarp();
                    }
                    if (lane == 0) g_cnt[c] = KNN;
                }
            }
        }
        __syncthreads();

        for (int p = 0; p < 2; p++) {
            sOut[tid] = 0;
            sOut[tid + 384] = 0;
            __syncthreads();

            const int q = 6 * p + (tid >> 6);
            const int j = 3 * m + (q >> 2);
            const int ev = q & 3;
            const int ii = cb + 140 * j;
            if (j <= JMAX && ii < 2048) {
                const int cc = ev * 2048 + ii;
                const int n = tid & 63;
                const bool active = (n < g_cnt[cc]);
                int* sOutC = sOut + (tid >> 6) * 128;

                const int idx = g_nbr[cc * KNN + n];
                const int row = ev * NP + idx;

                float rel[3];
                rel[0] = pos[row * 3 + 0] - g_centers[cc * 3 + 0];
                rel[1] = pos[row * 3 + 1] - g_centers[cc * 3 + 1];
                rel[2] = pos[row * 3 + 2] - g_centers[cc * 3 + 2];

                float h1[64];
                const float4* ur = (const float4*)(g_U + (size_t)row * 64);
#pragma unroll
                for (int h = 0; h < 2; h++) {
                    ull acc[16];
#pragma unroll
                    for (int qq = 0; qq < 8; qq++) {
                        const float4 u = ur[h * 8 + qq];
                        acc[2 * qq]     = packf2(u.x, u.y);
                        acc[2 * qq + 1] = packf2(u.z, u.w);
                    }
#pragma unroll
                    for (int i = 0; i < 3; i++) {
                        const ull a = pack2(rel[i]);
#pragma unroll
                        for (int k = 0; k < 8; k++) {
                            const ulonglong2 wv = *(const ulonglong2*)(sW1p + i * 64 + h * 32 + 4 * k);
                            FMA2(acc[2 * k], a, wv.x);
                            FMA2(acc[2 * k + 1], a, wv.y);
                        }
                    }
#pragma unroll
                    for (int k = 0; k < 16; k++) {
                        const float2 v = unpack2(acc[k]);
                        h1[h * 32 + 2 * k]     = fmaxf(v.x, 0.f);
                        h1[h * 32 + 2 * k + 1] = fmaxf(v.y, 0.f);
                    }
                }

                float h2[64];
#pragma unroll
                for (int qv = 0; qv < 4; qv++) {
                    ull acc[8];
#pragma unroll
                    for (int k = 0; k < 4; k++) {
                        const ulonglong2 bb = *(const ulonglong2*)(sb2 + qv * 16 + 4 * k);
                        acc[2 * k] = bb.x; acc[2 * k + 1] = bb.y;
                    }
#pragma unroll
                    for (int i = 0; i < 64; i++) {
                        const ull a = pack2(h1[i]);
#pragma unroll
                        for (int k = 0; k < 4; k++) {
                            const ulonglong2 wv = *(const ulonglong2*)(sW2 + i * 64 + qv * 16 + 4 * k);
                            FMA2(acc[2 * k], a, wv.x);
                            FMA2(acc[2 * k + 1], a, wv.y);
                        }
                    }
#pragma unroll
                    for (int k = 0; k < 8; k++) {
                        const float2 v = unpack2(acc[k]);
                        h2[qv * 16 + 2 * k]     = fmaxf(v.x, 0.f);
                        h2[qv * 16 + 2 * k + 1] = fmaxf(v.y, 0.f);
                    }
                }

#pragma unroll
                for (int qd = 0; qd < 4; qd++) {
                    ull acc[16];
#pragma unroll
                    for (int k = 0; k < 8; k++) {
                        const ulonglong2 bb = *(const ulonglong2*)(sb3 + qd * 32 + 4 * k);
                        acc[2 * k] = bb.x; acc[2 * k + 1] = bb.y;
                    }
#pragma unroll
                    for (int i = 0; i < 64; i++) {
                        const ull a = pack2(h2[i]);
#pragma unroll
                        for (int k = 0; k < 8; k++) {
                            const ulonglong2 wv = *(const ulonglong2*)(sW3 + i * 128 + qd * 32 + 4 * k);
                            FMA2(acc[2 * k], a, wv.x);
                            FMA2(acc[2 * k + 1], a, wv.y);
                        }
                    }
#pragma unroll
                    for (int k = 0; k < 16; k++) {
                        const float2 v = unpack2(acc[k]);
                        float v0 = active ? fmaxf(v.x, 0.f) : 0.f;
                        float v1 = active ? fmaxf(v.y, 0.f) : 0.f;
#pragma unroll
                        for (int o = 16; o >= 4; o >>= 1) {
                            v0 = fmaxf(v0, __shfl_xor_sync(0xffffffffu, v0, o));
                            v1 = fmaxf(v1, __shfl_xor_sync(0xffffffffu, v1, o));
                        }
                        if (lane < 4) {
                            atomicMax(sOutC + qd * 32 + 2 * k,     __float_as_int(v0));
                            atomicMax(sOutC + qd * 32 + 2 * k + 1, __float_as_int(v1));
                        }
                    }
                }
            }
            __syncthreads();

            for (int i2 = tid; i2 < 768; i2 += 384) {
                const int q2 = 6 * p + i2 / 128;
                const int j2 = 3 * m + (q2 >> 2);
                const int e2 = q2 & 3;
                const int i3 = cb + 140 * j2;
                if (j2 <= JMAX && i3 < 2048)
                    out[(size_t)(e2 * 2048 + i3) * 128 + (i2 & 127)] =
                        __int_as_float(sOut[i2]);
            }
            if (tid < 18) {
                const int q2 = 6 * p + tid / 3;
                const int j2 = 3 * m + (q2 >> 2);
                const int e2 = q2 & 3;
                const int i3 = cb + 140 * j2;
                if (j2 <= JMAX && i3 < 2048) {
                    const int c2 = e2 * 2048 + i3;
                    out[POS_OFF + (size_t)c2 * 3 + (tid % 3)] =
                        g_centers[c2 * 3 + (tid % 3)];
                }
            }
            if (tid < 6) {
                const int q2 = 6 * p + tid;
                const int j2 = 3 * m + (q2 >> 2);
                const int e2 = q2 & 3;
                const int i3 = cb + 140 * j2;
                if (j2 <= JMAX && i3 < 2048)
                    out[BATCH_OFF + e2 * 2048 + i3] = (float)e2;
            }
            __syncthreads();
        }
    }
}

// ============================================================================
extern "C" void kernel_launch(void* const* d_in, const int* in_sizes, int n_in,
                              void* d_out, int out_size) {
    const float* x   = (const float*)d_in[0];
    const float* pos = (const float*)d_in[1];
    const float* W1 = (const float*)d_in[3];
    const float* b1 = (const float*)d_in[4];
    const float* W2 = (const float*)d_in[5];
    const float* b2 = (const float*)d_in[6];
    const float* W3 = (const float*)d_in[7];
    const float* b3 = (const float*)d_in[8];
    float* out = (float*)d_out;

    const int smem = 4 * NP * 4;   // 131072 B
    cudaFuncSetAttribute(fused_kernel, cudaFuncAttributeMaxDynamicSharedMemorySize,
                         smem);
    fused_kernel<<<B_EV + NCONS, 384, smem>>>(x, pos, W1, b1, W2, b2, W3, b3, out);
}

// round 17
// speedup vs baseline: 1.5727x; 1.0041x over previous
#include <cuda_runtime.h>
#include <cstdint>

#define B_EV 4
#define NP 8192
#define MP 2048
#define KNN 64
#define NC (B_EV * MP)
#define R2F 0.04f
#define BIGF 1e10f
#define CAP 512
#define NCONS 140
#define JMAX 14
#define NGRP 5

#define XLEN (NC * 128)
#define POS_OFF XLEN
#define BATCH_OFF (XLEN + NC * 3)

typedef unsigned long long ull;

__device__ float g_centers[NC * 3];
__device__ int   g_nbr[NC * KNN];
__device__ int   g_cnt[NC];
__device__ float g_U[B_EV * NP * 64];
__device__ unsigned g_prog[B_EV * 32];   // padded: one 128B line per event
__device__ unsigned g_upre;              // monotonic: +NCONS per run

__device__ __forceinline__ float dist2(float dx, float dy, float dz) {
    return __fadd_rn(__fadd_rn(__fmul_rn(dx, dx), __fmul_rn(dy, dy)),
                     __fmul_rn(dz, dz));
}

#define FMA2(acc, a, b) \
    asm("fma.rn.f32x2 %0, %1, %2, %0;" : "+l"(acc) : "l"(a), "l"(b))
#define ADD2(dst, a, b) \
    asm("add.rn.f32x2 %0, %1, %2;" : "=l"(dst) : "l"(a), "l"(b))
#define MUL2(dst, a, b) \
    asm("mul.rn.f32x2 %0, %1, %2;" : "=l"(dst) : "l"(a), "l"(b))

__device__ __forceinline__ ull pack2(float v) {
    ull r; asm("mov.b64 %0, {%1, %1};" : "=l"(r) : "r"(__float_as_uint(v)));
    return r;
}
__device__ __forceinline__ ull packf2(float lo, float hi) {
    ull r; asm("mov.b64 %0, {%1, %2};" : "=l"(r)
        : "r"(__float_as_uint(lo)), "r"(__float_as_uint(hi)));
    return r;
}
__device__ __forceinline__ float2 unpack2(ull p) {
    unsigned lo, hi; asm("mov.b64 {%0, %1}, %2;" : "=r"(lo), "=r"(hi) : "l"(p));
    return make_float2(__uint_as_float(lo), __uint_as_float(hi));
}

__device__ __forceinline__ float max22_tree(const float* d) {
    float m[11];
#pragma unroll
    for (int k = 0; k < 11; k++) m[k] = fmaxf(d[2 * k], d[2 * k + 1]);
    const float n0 = fmaxf(m[0], m[1]), n1 = fmaxf(m[2], m[3]);
    const float n2 = fmaxf(m[4], m[5]), n3 = fmaxf(m[6], m[7]);
    const float n4 = fmaxf(m[8], m[9]);
    return fmaxf(fmaxf(fmaxf(n0, n1), fmaxf(n2, n3)), fmaxf(n4, m[10]));
}

// ============================================================================
// Fused persistent kernel. Blocks 0..3: FPS (512-cell Morton sort, warp-11
// publisher). Blocks 4..143: consumers (byte-identical to R16, bit-exact).
// ============================================================================
__global__ __launch_bounds__(384) void fused_kernel(
    const float* __restrict__ x, const float* __restrict__ pos,
    const float* __restrict__ W1, const float* __restrict__ b1,
    const float* __restrict__ W2, const float* __restrict__ b2,
    const float* __restrict__ W3, const float* __restrict__ b3,
    float* __restrict__ out)
{
    extern __shared__ float dyn[];
    const int tid = threadIdx.x;
    const int lane = tid & 31;
    const int wid = tid >> 5;

    if (blockIdx.x < B_EV) {
        // ==================== FPS role ====================
        const int e = blockIdx.x;
        const float* pe = pos + (size_t)e * NP * 3;
        float* sx = dyn;
        float* sy = sx + NP;
        float* sz = sy + NP;
        int*   sidx = (int*)(sz + NP);
        __shared__ int s_cnt[512];
        __shared__ ull s_key[2][16];

        for (int i = tid; i < 512; i += 384) s_cnt[i] = 0;
        if (tid < 8) s_key[tid >> 2][12 + (tid & 3)] = 0ull;
        __syncthreads();

        float ox[22], oy[22], oz[22];
        int cel[22];
#pragma unroll
        for (int j = 0; j < 22; j++) {
            const bool act = (j < 21) || (tid < 128);
            if (act) {
                const int g = tid + j * 384;
                ox[j] = pe[3 * g]; oy[j] = pe[3 * g + 1]; oz[j] = pe[3 * g + 2];
                int ix = (int)(ox[j] * 8.f); ix = ix < 7 ? ix : 7;
                int iy = (int)(oy[j] * 8.f); iy = iy < 7 ? iy : 7;
                int iz = (int)(oz[j] * 8.f); iz = iz < 7 ? iz : 7;
                cel[j] = ((ix >> 2) << 8) | ((iy >> 2) << 7) | ((iz >> 2) << 6) |
                         (((ix >> 1) & 1) << 5) | (((iy >> 1) & 1) << 4) |
                         (((iz >> 1) & 1) << 3) |
                         ((ix & 1) << 2) | ((iy & 1) << 1) | (iz & 1);
                atomicAdd(&s_cnt[cel[j]], 1);
            }
        }
        __syncthreads();
        if (tid == 0) {
            int run = 0;
            for (int c2 = 0; c2 < 512; c2++) { const int v = s_cnt[c2]; s_cnt[c2] = run; run += v; }
        }
        __syncthreads();
#pragma unroll
        for (int j = 0; j < 22; j++) {
            const bool act = (j < 21) || (tid < 128);
            if (act) {
                const int p = atomicAdd(&s_cnt[cel[j]], 1);
                sx[p] = ox[j]; sy[p] = oy[j]; sz[p] = oz[j];
                sidx[p] = tid + j * 384;
            }
        }
        __syncthreads();

        ull pxp[11], pyp[11], pzp[11];
        int io[22];
        float d[22];
        float tbnx = 2.f, tbny = 2.f, tbnz = 2.f, tbxx = -1.f, tbxy = -1.f, tbxz = -1.f;
        const int base = tid * 22;
#pragma unroll
        for (int j = 0; j < 11; j++) {
            int s0 = base + 2 * j;     s0 = s0 < 8191 ? s0 : 8191;
            int s1 = base + 2 * j + 1; s1 = s1 < 8191 ? s1 : 8191;
            const float ax = sx[s0], bx = sx[s1];
            const float ay = sy[s0], by = sy[s1];
            const float az = sz[s0], bz = sz[s1];
            pxp[j] = packf2(ax, bx); pyp[j] = packf2(ay, by); pzp[j] = packf2(az, bz);
            io[2 * j] = sidx[s0]; io[2 * j + 1] = sidx[s1];
            tbnx = fminf(tbnx, fminf(ax, bx)); tbxx = fmaxf(tbxx, fmaxf(ax, bx));
            tbny = fminf(tbny, fminf(ay, by)); tbxy = fmaxf(tbxy, fmaxf(ay, by));
            tbnz = fminf(tbnz, fminf(az, bz)); tbxz = fmaxf(tbxz, fmaxf(az, bz));
        }
        __syncthreads();

#pragma unroll
        for (int j = 0; j < 22; j++) {
            const bool act = (j < 21) || (tid < 128);
            if (act) {
                const int g = tid + j * 384;
                sx[g] = ox[j]; sy[g] = oy[j]; sz[g] = oz[j];
            }
        }

        const float c0x = pe[0], c0y = pe[1], c0z = pe[2];
        {
            const ull ncx = pack2(-c0x), ncy = pack2(-c0y), ncz = pack2(-c0z);
#pragma unroll
            for (int j = 0; j < 11; j++) {
                ull dx, dy, dz, qx, qy, qz, s1v, s2v;
                ADD2(dx, pxp[j], ncx); ADD2(dy, pyp[j], ncy); ADD2(dz, pzp[j], ncz);
                MUL2(qx, dx, dx); MUL2(qy, dy, dy); MUL2(qz, dz, dz);
                ADD2(s1v, qx, qy); ADD2(s2v, s1v, qz);
                const float2 f = unpack2(s2v);
                d[2 * j] = f.x; d[2 * j + 1] = f.y;
            }
        }
        ull mykey;
        float tdmax;
        {
            const float mm = max22_tree(d);
            tdmax = mm;
            const unsigned wb = __reduce_max_sync(0xffffffffu, __float_as_uint(mm));
            unsigned cl = 0;
#pragma unroll
            for (int t = 0; t < 22; t++)
                if (__float_as_uint(d[t]) == wb) cl = max(cl, ~(unsigned)io[t]);
            const unsigned wl = __reduce_max_sync(0xffffffffu, cl);
            mykey = ((ull)wb << 32) | wl;
        }
        if (lane == 0) s_key[0][wid] = mykey;
        if (tid == 352) {
            g_centers[(e * MP) * 3 + 0] = c0x;
            g_centers[(e * MP) * 3 + 1] = c0y;
            g_centers[(e * MP) * 3 + 2] = c0z;
        }

        for (int i = 1; i < MP; i++) {
            __syncthreads();
            const ull kk = s_key[(i - 1) & 1][lane & 15];
            const unsigned hi = (unsigned)(kk >> 32);
            const unsigned lo = (unsigned)kk;
            const unsigned mhi = __reduce_max_sync(0xffffffffu, hi);
            const unsigned mlo = __reduce_max_sync(0xffffffffu, (hi == mhi) ? lo : 0u);
            const int nxt = (int)(~mlo);

            const float nx = sx[nxt], ny = sy[nxt], nz = sz[nxt];
            if (tid == 352) {      // publisher off the pacing warp
                g_centers[(e * MP + i) * 3 + 0] = nx;
                g_centers[(e * MP + i) * 3 + 1] = ny;
                g_centers[(e * MP + i) * 3 + 2] = nz;
                if ((i & 15) == 15) {
                    __threadfence();
                    atomicAdd(&g_prog[e * 32], 16u);
                }
            }

            const float lbx = fmaxf(fmaxf(tbnx - nx, nx - tbxx), 0.f);
            const float lby = fmaxf(fmaxf(tbny - ny, ny - tbxy), 0.f);
            const float lbz = fmaxf(fmaxf(tbnz - nz, nz - tbxz), 0.f);
            const float lb2 = ((lbx * lbx + lby * lby) + lbz * lbz) * 0.999999f;
            const bool needs = (lb2 < tdmax);

            if (__any_sync(0xffffffffu, needs)) {
                const ull ncx = pack2(-nx), ncy = pack2(-ny), ncz = pack2(-nz);
#pragma unroll
                for (int j = 0; j < 11; j++) {
                    ull dx, dy, dz, qx, qy, qz, s1v, s2v;
                    ADD2(dx, pxp[j], ncx); ADD2(dy, pyp[j], ncy); ADD2(dz, pzp[j], ncz);
                    MUL2(qx, dx, dx); MUL2(qy, dy, dy); MUL2(qz, dz, dz);
                    ADD2(s1v, qx, qy); ADD2(s2v, s1v, qz);
                    const float2 f = unpack2(s2v);
                    d[2 * j]     = fminf(d[2 * j], f.x);
                    d[2 * j + 1] = fminf(d[2 * j + 1], f.y);
                }
                const float mm = max22_tree(d);
                tdmax = mm;
                const unsigned wb = __reduce_max_sync(0xffffffffu, __float_as_uint(mm));
                unsigned cl = 0;
#pragma unroll
                for (int t = 0; t < 22; t++)
                    if (__float_as_uint(d[t]) == wb) cl = max(cl, ~(unsigned)io[t]);
                const unsigned wl = __reduce_max_sync(0xffffffffu, cl);
                mykey = ((ull)wb << 32) | wl;
            }
            if (lane == 0) s_key[i & 1][wid] = mykey;
        }
        return;
    }

    // ======================= Consumer role (R16, bit-exact) =======================
    const int cb = blockIdx.x - B_EV;
    float* sW1p = dyn;
    float* sW2  = dyn + 192;
    float* sW3  = dyn + 4288;
    float* sb2  = dyn + 12480;
    float* sb3  = dyn + 12544;
    float* bqd  = dyn + 12672;
    int*   bqi  = (int*)(dyn + 18816);
    int*   sOut = (int*)(dyn + 24960);
    __shared__ unsigned s_base[4];
    __shared__ unsigned s_ub;

    if (tid < 4) s_base[tid] = (*((volatile unsigned*)&g_prog[tid * 32]) / MP) * MP;
    if (tid == 4) s_ub = (*((volatile unsigned*)&g_upre) / NCONS) * NCONS;

    for (int i = tid; i < 2048; i += 384) sW2[i] = W1[i];
    if (tid < 64) sb2[tid] = b1[tid];
    __syncthreads();
    {
        const int r = cb * 235 + tid;
        if (tid < 235 && r < B_EV * NP) {
            float inv[32];
            const float4* xr = (const float4*)(x + (size_t)r * 32);
#pragma unroll
            for (int q = 0; q < 8; q++) {
                const float4 v = xr[q];
                inv[4 * q] = v.x; inv[4 * q + 1] = v.y;
                inv[4 * q + 2] = v.z; inv[4 * q + 3] = v.w;
            }
            float4* ur = (float4*)(g_U + (size_t)r * 64);
#pragma unroll
            for (int h = 0; h < 2; h++) {
                ull acc[16];
#pragma unroll
                for (int k = 0; k < 8; k++) {
                    const ulonglong2 bb = *(const ulonglong2*)(sb2 + h * 32 + 4 * k);
                    acc[2 * k] = bb.x; acc[2 * k + 1] = bb.y;
                }
#pragma unroll
                for (int i2 = 0; i2 < 32; i2++) {
                    const ull a = pack2(inv[i2]);
#pragma unroll
                    for (int k = 0; k < 8; k++) {
                        const ulonglong2 wv = *(const ulonglong2*)(sW2 + i2 * 64 + h * 32 + 4 * k);
                        FMA2(acc[2 * k], a, wv.x);
                        FMA2(acc[2 * k + 1], a, wv.y);
                    }
                }
#pragma unroll
                for (int k = 0; k < 8; k++) {
                    const float2 v0 = unpack2(acc[2 * k]);
                    const float2 v1 = unpack2(acc[2 * k + 1]);
                    ur[h * 8 + k] = make_float4(v0.x, v0.y, v1.x, v1.y);
                }
            }
        }
    }
    __threadfence();
    __syncthreads();
    if (tid == 0) atomicAdd(&g_upre, 1u);

    __syncthreads();
    for (int i = tid; i < 192; i += 384) sW1p[i] = W1[2048 + i];
    for (int i = tid; i < 4096; i += 384) sW2[i] = W2[i];
    for (int i = tid; i < 8192; i += 384) sW3[i] = W3[i];
    if (tid < 64) sb2[tid] = b2[tid];
    if (tid < 128) sb3[tid] = b3[tid];
    if (tid == 0) {
        while (*((volatile unsigned*)&g_upre) < s_ub + NCONS) __nanosleep(1024);
    }
    __syncthreads();
    __threadfence();

    for (int m = 0; m < NGRP; m++) {
        int jv = 3 * m + 2; if (jv > JMAX) jv = JMAX;
        while (cb + 140 * jv >= 2048) jv--;
        const int ith = cb + 140 * jv;
        if (tid < 4) {
            const unsigned thr = s_base[tid] + (unsigned)ith + 1u;
            while (*((volatile unsigned*)&g_prog[tid * 32]) < thr) __nanosleep(1024);
        }
        __syncthreads();
        __threadfence();

        {
            const int j = 3 * m + (wid >> 2);
            const int ev = wid & 3;
            const int ii = cb + 140 * j;
            if (j <= JMAX && ii < 2048) {
                const int c = ev * 2048 + ii;
                const float* pe = pos + (size_t)ev * NP * 3;
                const float cx = g_centers[c * 3 + 0];
                const float cy = g_centers[c * 3 + 1];
                const float cz = g_centers[c * 3 + 2];
                float* d2 = bqd + wid * CAP;
                int*   iv = bqi + wid * CAP;
                int cnt = 0;
                const unsigned lmask = (1u << lane) - 1u;
                for (int jj = lane; jj < NP; jj += 32) {
                    const float dv = dist2(pe[3 * jj] - cx, pe[3 * jj + 1] - cy,
                                           pe[3 * jj + 2] - cz);
                    const bool inr = (dv <= R2F);
                    const unsigned mb = __ballot_sync(0xffffffffu, inr);
                    if (inr) {
                        const int slot = cnt + __popc(mb & lmask);
                        if (slot < CAP) { d2[slot] = dv; iv[slot] = jj; }
                    }
                    cnt += __popc(mb);
                }
                const int C = (cnt < CAP) ? cnt : CAP;
                if (C <= KNN) {
                    for (int k = lane; k < KNN; k += 32)
                        g_nbr[c * KNN + k] = (k < C) ? iv[k] : 0;
                    if (lane == 0) g_cnt[c] = C;
                } else {
                    for (int s = 0; s < KNN; s++) {
                        ull best = ~0ull;
                        for (int t = lane; t < C; t += 32) {
                            const ull key = ((ull)__float_as_uint(d2[t]) << 32) | (unsigned)t;
                            best = (key < best) ? key : best;
                        }
#pragma unroll
                        for (int o = 16; o > 0; o >>= 1) {
                            const ull other = __shfl_down_sync(0xffffffffu, best, o);
                            best = (other < best) ? other : best;
                        }
                        best = __shfl_sync(0xffffffffu, best, 0);
                        const int slot = (int)(unsigned)best;
                        if (lane == 0) {
                            g_nbr[c * KNN + s] = iv[slot];
                            d2[slot] = BIGF;
                        }
                        __syncwarp();
                    }
                    if (lane == 0) g_cnt[c] = KNN;
                }
            }
        }
        __syncthreads();

        for (int p = 0; p < 2; p++) {
            sOut[tid] = 0;
            sOut[tid + 384] = 0;
            __syncthreads();

            const int q = 6 * p + (tid >> 6);
            const int j = 3 * m + (q >> 2);
            const int ev = q & 3;
            const int ii = cb + 140 * j;
            if (j <= JMAX && ii < 2048) {
                const int cc = ev * 2048 + ii;
                const int n = tid & 63;
                const bool active = (n < g_cnt[cc]);
                int* sOutC = sOut + (tid >> 6) * 128;

                const int idx = g_nbr[cc * KNN + n];
                const int row = ev * NP + idx;

                float rel[3];
                rel[0] = pos[row * 3 + 0] - g_centers[cc * 3 + 0];
                rel[1] = pos[row * 3 + 1] - g_centers[cc * 3 + 1];
                rel[2] = pos[row * 3 + 2] - g_centers[cc * 3 + 2];

                float h1[64];
                const float4* ur = (const float4*)(g_U + (size_t)row * 64);
#pragma unroll
                for (int h = 0; h < 2; h++) {
                    ull acc[16];
#pragma unroll
                    for (int qq = 0; qq < 8; qq++) {
                        const float4 u = ur[h * 8 + qq];
                        acc[2 * qq]     = packf2(u.x, u.y);
                        acc[2 * qq + 1] = packf2(u.z, u.w);
                    }
#pragma unroll
                    for (int i = 0; i < 3; i++) {
                        const ull a = pack2(rel[i]);
#pragma unroll
                        for (int k = 0; k < 8; k++) {
                            const ulonglong2 wv = *(const ulonglong2*)(sW1p + i * 64 + h * 32 + 4 * k);
                            FMA2(acc[2 * k], a, wv.x);
                            FMA2(acc[2 * k + 1], a, wv.y);
                        }
                    }
#pragma unroll
                    for (int k = 0; k < 16; k++) {
                        const float2 v = unpack2(acc[k]);
                        h1[h * 32 + 2 * k]     = fmaxf(v.x, 0.f);
                        h1[h * 32 + 2 * k + 1] = fmaxf(v.y, 0.f);
                    }
                }

                float h2[64];
#pragma unroll
                for (int qv = 0; qv < 4; qv++) {
                    ull acc[8];
#pragma unroll
                    for (int k = 0; k < 4; k++) {
                        const ulonglong2 bb = *(const ulonglong2*)(sb2 + qv * 16 + 4 * k);
                        acc[2 * k] = bb.x; acc[2 * k + 1] = bb.y;
                    }
#pragma unroll
                    for (int i = 0; i < 64; i++) {
                        const ull a = pack2(h1[i]);
#pragma unroll
                        for (int k = 0; k < 4; k++) {
                            const ulonglong2 wv = *(const ulonglong2*)(sW2 + i * 64 + qv * 16 + 4 * k);
                            FMA2(acc[2 * k], a, wv.x);
                            FMA2(acc[2 * k + 1], a, wv.y);
                        }
                    }
#pragma unroll
                    for (int k = 0; k < 8; k++) {
                        const float2 v = unpack2(acc[k]);
                        h2[qv * 16 + 2 * k]     = fmaxf(v.x, 0.f);
                        h2[qv * 16 + 2 * k + 1] = fmaxf(v.y, 0.f);
                    }
                }

#pragma unroll
                for (int qd = 0; qd < 4; qd++) {
                    ull acc[16];
#pragma unroll
                    for (int k = 0; k < 8; k++) {
                        const ulonglong2 bb = *(const ulonglong2*)(sb3 + qd * 32 + 4 * k);
                        acc[2 * k] = bb.x; acc[2 * k + 1] = bb.y;
                    }
#pragma unroll
                    for (int i = 0; i < 64; i++) {
                        const ull a = pack2(h2[i]);
#pragma unroll
                        for (int k = 0; k < 8; k++) {
                            const ulonglong2 wv = *(const ulonglong2*)(sW3 + i * 128 + qd * 32 + 4 * k);
                            FMA2(acc[2 * k], a, wv.x);
                            FMA2(acc[2 * k + 1], a, wv.y);
                        }
                    }
#pragma unroll
                    for (int k = 0; k < 16; k++) {
                        const float2 v = unpack2(acc[k]);
                        float v0 = active ? fmaxf(v.x, 0.f) : 0.f;
                        float v1 = active ? fmaxf(v.y, 0.f) : 0.f;
#pragma unroll
                        for (int o = 16; o >= 4; o >>= 1) {
                            v0 = fmaxf(v0, __shfl_xor_sync(0xffffffffu, v0, o));
                            v1 = fmaxf(v1, __shfl_xor_sync(0xffffffffu, v1, o));
                        }
                        if (lane < 4) {
                            atomicMax(sOutC + qd * 32 + 2 * k,     __float_as_int(v0));
                            atomicMax(sOutC + qd * 32 + 2 * k + 1, __float_as_int(v1));
                        }
                    }
                }
            }
            __syncthreads();

            for (int i2 = tid; i2 < 768; i2 += 384) {
                const int q2 = 6 * p + i2 / 128;
                const int j2 = 3 * m + (q2 >> 2);
                const int e2 = q2 & 3;
                const int i3 = cb + 140 * j2;
                if (j2 <= JMAX && i3 < 2048)
                    out[(size_t)(e2 * 2048 + i3) * 128 + (i2 & 127)] =
                        __int_as_float(sOut[i2]);
            }
            if (tid < 18) {
                const int q2 = 6 * p + tid / 3;
                const int j2 = 3 * m + (q2 >> 2);
                const int e2 = q2 & 3;
                const int i3 = cb + 140 * j2;
                if (j2 <= JMAX && i3 < 2048) {
                    const int c2 = e2 * 2048 + i3;
                    out[POS_OFF + (size_t)c2 * 3 + (tid % 3)] =
                        g_centers[c2 * 3 + (tid % 3)];
                }
            }
            if (tid < 6) {
                const int q2 = 6 * p + tid;
                const int j2 = 3 * m + (q2 >> 2);
                const int e2 = q2 & 3;
                const int i3 = cb + 140 * j2;
                if (j2 <= JMAX && i3 < 2048)
                    out[BATCH_OFF + e2 * 2048 + i3] = (float)e2;
            }
            __syncthreads();
        }
    }
}

// ============================================================================
extern "C" void kernel_launch(void* const* d_in, const int* in_sizes, int n_in,
                              void* d_out, int out_size) {
    const float* x   = (const float*)d_in[0];
    const float* pos = (const float*)d_in[1];
    const float* W1 = (const float*)d_in[3];
    const float* b1 = (const float*)d_in[4];
    const float* W2 = (const float*)d_in[5];
    const float* b2 = (const float*)d_in[6];
    const float* W3 = (const float*)d_in[7];
    const float* b3 = (const float*)d_in[8];
    float* out = (float*)d_out;

    const int smem = 4 * NP * 4;   // 131072 B
    cudaFuncSetAttribute(fused_kernel, cudaFuncAttributeMaxDynamicSharedMemorySize,
                         smem);
    fused_kernel<<<B_EV + NCONS, 384, smem>>>(x, pos, W1, b1, W2, b2, W3, b3, out);
}